// round 10
// baseline (speedup 1.0000x reference)
#include <cuda_runtime.h>
#include <cstdint>

// Shape (from reference setup_inputs): B=64, S=1024, D=512, T=2048.
// S, D, T re-derived from in_sizes/out_size at launch; B fixed.
#define BATCH 64
#define MAX_S 1024
#define MAX_T 4096
#define ROWS  8        // output rows per 128-thread group (T must be divisible)

// Scratch (no allocations allowed).
__device__ int g_idx[BATCH * MAX_T];   // idx[b][t] = source row for output slot t
__device__ int g_len[BATCH];           // total length per batch

// ---------------------------------------------------------------------------
// Kernel 1 (prep): per-batch inclusive scan via warp shuffles, inverse-map
// scatter (source s owns output slots [cum[s]-dur[s], cum[s])), mask write.
// One block per batch, S=1024 threads. Body identical to the R8 passing
// version; only the PDL trigger at the end is new.
// ---------------------------------------------------------------------------
__global__ void prep_kernel(const int* __restrict__ dur,
                            float* __restrict__ mask, int S, int T) {
    __shared__ int warp_sums[32];
    __shared__ int s_len;
    const int tid = threadIdx.x;
    const int b   = blockIdx.x;
    const int ln  = tid & 31;

    const int d = dur[b * S + tid];

    // intra-warp inclusive scan
    int v = d;
    #pragma unroll
    for (int o = 1; o < 32; o <<= 1) {
        int n = __shfl_up_sync(0xffffffffu, v, o);
        if (ln >= o) v += n;
    }
    if (ln == 31) warp_sums[tid >> 5] = v;
    __syncthreads();

    // scan of the 32 warp totals by warp 0
    if (tid < 32) {
        int w = warp_sums[tid];
        #pragma unroll
        for (int o = 1; o < 32; o <<= 1) {
            int n = __shfl_up_sync(0xffffffffu, w, o);
            if (tid >= o) w += n;
        }
        warp_sums[tid] = w;
        if (tid == 31) s_len = w;
    }
    __syncthreads();

    const int base  = (tid >= 32) ? warp_sums[(tid >> 5) - 1] : 0;
    const int end   = base + v;          // inclusive cumsum
    const int start = end - d;
    const int len   = s_len;

    if (tid == 0) g_len[b] = len;

    // mask for this batch (coalesced; T/S = 2 iterations)
    for (int p = tid; p < T; p += S)
        mask[b * T + p] = (p >= len) ? 1.0f : 0.0f;

    // inverse-map scatter: slots [start, min(end, T)) get source index tid
    int* __restrict__ idx = g_idx + b * T;
    const int stop = min(end, T);
    for (int p = start; p < stop; ++p) idx[p] = tid;
    // Slots in [len, T) are never read (gather zero-fills them).

    // PDL release: make all writes visible, then allow the dependent grid
    // (gather) to pass its cudaGridDependencySynchronize().
    __threadfence();
    cudaTriggerProgrammaticLaunchCompletion();
}

// ---------------------------------------------------------------------------
// Kernel 2: gather/copy (R8 body verbatim + PDL wait). One 128-thread group
// per ROWS consecutive output rows; two groups per 256-thread block. Launched
// with programmatic stream serialization: blocks come up concurrently with
// prep, do their setup, then hardware-wait for prep's trigger before touching
// g_idx / g_len.
// ---------------------------------------------------------------------------
__global__ void gather_kernel(const float* __restrict__ x,
                              float* __restrict__ out,
                              int S, int T, int D) {
    const int group = blockIdx.x * 2 + (threadIdx.x >> 7);
    const int lane  = threadIdx.x & 127;
    const int row0  = group * ROWS;            // first (b,t) row of this group
    const int b     = row0 / T;                // ROWS divides T -> same batch
    const int t0    = row0 - b * T;

    // Address setup (independent of prep's output) before the dependency wait.
    const float4* __restrict__ xv =
        reinterpret_cast<const float4*>(x + (size_t)b * S * D) + lane;
    float4* __restrict__ dst =
        reinterpret_cast<float4*>(out + (size_t)row0 * D) + lane;
    const int strideV = D >> 2;                // float4s per row (=128)

    // Wait until the prep grid has triggered completion (HW grid dependency).
    cudaGridDependencySynchronize();

    const int len = g_len[b];

    // source indices: 32B broadcast (values for masked slots unused; any
    // stale value there is a previously-written index in [0, S), in-bounds)
    const int4* __restrict__ ip =
        reinterpret_cast<const int4*>(g_idx + row0);
    const int4 i0 = __ldg(ip);
    const int4 i1 = __ldg(ip + 1);
    const int idx[ROWS] = {i0.x, i0.y, i0.z, i0.w, i1.x, i1.y, i1.z, i1.w};

    // ROWS independent loads in flight
    float4 v[ROWS];
    #pragma unroll
    for (int r = 0; r < ROWS; ++r) {
        if (t0 + r < len)
            v[r] = xv[(size_t)idx[r] * strideV];
        else
            v[r] = make_float4(0.f, 0.f, 0.f, 0.f);
    }

    #pragma unroll
    for (int r = 0; r < ROWS; ++r)
        __stcs(dst + (size_t)r * strideV, v[r]);
}

// ---------------------------------------------------------------------------
extern "C" void kernel_launch(void* const* d_in, const int* in_sizes, int n_in,
                              void* d_out, int out_size) {
    const float* x   = (const float*)d_in[0];
    const int*   dur = (const int*)d_in[1];

    const int BS = in_sizes[1];               // B*S = 65536
    const int B  = BATCH;                     // 64
    const int S  = BS / B;                    // 1024
    const int D  = in_sizes[0] / BS;          // 512
    const int T  = out_size / (B * (D + 1));  // 2048

    float* out  = (float*)d_out;
    float* mask = out + (size_t)B * T * D;

    prep_kernel<<<B, S>>>(dur, mask, S, T);

    // Gather with programmatic dependent launch: starts while prep runs,
    // blocks in cudaGridDependencySynchronize() until prep triggers.
    cudaLaunchConfig_t cfg = {};
    cfg.gridDim  = dim3((unsigned)((B * T / ROWS) / 2), 1, 1);
    cfg.blockDim = dim3(256, 1, 1);
    cfg.dynamicSmemBytes = 0;
    cfg.stream = 0;   // legacy default stream (same one the harness captures)
    cudaLaunchAttribute attr[1];
    attr[0].id = cudaLaunchAttributeProgrammaticStreamSerialization;
    attr[0].val.programmaticStreamSerializationAllowed = 1;
    cfg.attrs = attr;
    cfg.numAttrs = 1;
    cudaLaunchKernelEx(&cfg, gather_kernel, x, out, S, T, D);
}